// round 1
// baseline (speedup 1.0000x reference)
#include <cuda_runtime.h>

// HSMNet feature-volume construction, 4 scales fused into one launch.
// out[b,c,d,h,w] = (w>=d) ? |ref[b,c,h,w] - tgt[b,c,h,w-d]| : 0
// B*C = 64 planes at every scale. Scales:
//   s0: D=6,  H=12, W=20   (conv40/41)  ->  92160 elems
//   s1: D=12, H=24, W=40   (conv30/31)  -> 737280 elems
//   s2: D=24, H=48, W=80   (conv20/21)  -> 5898240 elems
//   s3: D=48, H=96, W=160  (conv10/11)  -> 47185920 elems
// Total 53,913,600 fp32 = 215.7 MB written; ~10.4 MB read (L2-resident).
// Purely HBM-write-bound.

namespace {

constexpr int BC = 64;  // B*C

// float4-unit element counts per scale
constexpr int N4_0 = BC * 6  * 12 * 20  / 4;  //    23040
constexpr int N4_1 = BC * 12 * 24 * 40  / 4;  //   184320
constexpr int N4_2 = BC * 24 * 48 * 80  / 4;  //  1474560
constexpr int N4_3 = BC * 48 * 96 * 160 / 4;  // 11796480

// cumulative boundaries (float4 units)
constexpr int CUM0 = N4_0;                 //    23040
constexpr int CUM1 = CUM0 + N4_1;          //   207360
constexpr int CUM2 = CUM1 + N4_2;          //  1681920
constexpr int CUM3 = CUM2 + N4_3;          // 13478400 (total float4s)

constexpr int THREADS = 256;
constexpr int BLOCKS  = (CUM3 + THREADS - 1) / THREADS;  // 52650 exact

template <int D, int H, int W>
__device__ __forceinline__ void feat_vol_elem(const float* __restrict__ ref,
                                              const float* __restrict__ tgt,
                                              float* __restrict__ out,
                                              int i /* float4 index within scale */) {
    constexpr int W4 = W / 4;
    // decompose: i*4 = ((bc*D + d)*H + h)*W + w0  with compile-time divisors
    int w4 = i % W4;
    int t  = i / W4;
    int h  = t % H;
    t      = t / H;
    int d  = t % D;
    int bc = t / D;

    const int base = (bc * H + h) * W;
    const int w0   = w4 * 4;

    const float4 r = *reinterpret_cast<const float4*>(ref + base + w0);
    const float* __restrict__ trow = tgt + base;

    float rv[4] = {r.x, r.y, r.z, r.w};
    float o[4];
#pragma unroll
    for (int j = 0; j < 4; ++j) {
        const int w  = w0 + j;
        const int tw = w - d;
        // reference: idx = clip(w-d,0,W-1); result masked to 0 when w<d.
        o[j] = (tw >= 0) ? fabsf(rv[j] - trow[tw]) : 0.0f;
    }

    *reinterpret_cast<float4*>(out + (size_t)i * 4) =
        make_float4(o[0], o[1], o[2], o[3]);
}

__global__ void __launch_bounds__(THREADS)
hsmnet_featvol_kernel(const float* __restrict__ c40, const float* __restrict__ c41,
                      const float* __restrict__ c30, const float* __restrict__ c31,
                      const float* __restrict__ c20, const float* __restrict__ c21,
                      const float* __restrict__ c10, const float* __restrict__ c11,
                      float* __restrict__ out) {
    const int gid = blockIdx.x * THREADS + threadIdx.x;
    if (gid >= CUM3) return;

    if (gid < CUM0) {
        feat_vol_elem<6, 12, 20>(c40, c41, out, gid);
    } else if (gid < CUM1) {
        feat_vol_elem<12, 24, 40>(c30, c31, out + 4 * CUM0, gid - CUM0);
    } else if (gid < CUM2) {
        feat_vol_elem<24, 48, 80>(c20, c21, out + 4 * CUM1, gid - CUM1);
    } else {
        feat_vol_elem<48, 96, 160>(c10, c11, out + 4 * CUM2, gid - CUM2);
    }
}

}  // namespace

extern "C" void kernel_launch(void* const* d_in, const int* in_sizes, int n_in,
                              void* d_out, int out_size) {
    const float* c40 = (const float*)d_in[0];
    const float* c41 = (const float*)d_in[1];
    const float* c30 = (const float*)d_in[2];
    const float* c31 = (const float*)d_in[3];
    const float* c20 = (const float*)d_in[4];
    const float* c21 = (const float*)d_in[5];
    const float* c10 = (const float*)d_in[6];
    const float* c11 = (const float*)d_in[7];
    // d_in[8] is maxdisp (=384); the per-scale D values (384/64, /32, /16, /8)
    // are baked in as template constants.
    float* out = (float*)d_out;

    hsmnet_featvol_kernel<<<BLOCKS, THREADS>>>(c40, c41, c30, c31,
                                               c20, c21, c10, c11, out);
}

// round 2
// speedup vs baseline: 1.4901x; 1.4901x over previous
#include <cuda_runtime.h>

// HSMNet feature-volume, 4 scales fused, d/w micro-tiled.
// out[bc,d,h,w] = (w>=d) ? |ref[bc,h,w] - tgt[bc,h,w-d]| : 0
// Scales: s0 D=6 H=12 W=20 | s1 D=12 H=24 W=40 | s2 D=24 H=48 W=80 | s3 D=48 H=96 W=160
// 215.7 MB written, ~10.4 MB read (L2-resident). Goal: DRAM-write-bound.
//
// s1..s3: one thread = 4x4 (d,w) tile. e = w0-d0 is a multiple of 4, so the
// 7-float tgt window [e-3, e+3] sits inside two ALIGNED float4 loads.
// Per 64B output: 3 coalesced LDG.128 + 4 coalesced STG.128 (vs 20 loads before).

namespace {

constexpr int BC = 64;

// ---- scale 0: per-float4-element path (tiny: 0.17% of work) ----
constexpr int G0 = BC * 6 * 12 * 20 / 4;          // 23040

// ---- scales 1..3: 4x4 tile groups: BC * (D/4) * H * (W/4) ----
constexpr int G1 = BC * (12 / 4) * 24 * (40 / 4);   //   46080
constexpr int G2 = BC * (24 / 4) * 48 * (80 / 4);   //  368640
constexpr int G3 = BC * (48 / 4) * 96 * (160 / 4);  // 2949120

constexpr int CA = G0;            //   23040
constexpr int CB = CA + G1;       //   69120
constexpr int CC = CB + G2;       //  437760
constexpr int CD = CC + G3;       // 3386880  (total threads)

// output float offsets per scale
constexpr int O0 = 0;
constexpr int O1 = O0 + BC * 6 * 12 * 20;     //   92160
constexpr int O2 = O1 + BC * 12 * 24 * 40;    //  829440
constexpr int O3 = O2 + BC * 24 * 48 * 80;    // 6727680

constexpr int THREADS = 256;
constexpr int BLOCKS  = CD / THREADS;         // 13230 exact

// scale-0 fallback: one float4 of output per thread, scalar tgt loads
template <int D, int H, int W>
__device__ __forceinline__ void feat_vol_elem(const float* __restrict__ ref,
                                              const float* __restrict__ tgt,
                                              float* __restrict__ out, int i) {
    constexpr int W4 = W / 4;
    int w4 = i % W4;
    int t  = i / W4;
    int h  = t % H;  t /= H;
    int d  = t % D;
    int bc = t / D;

    const int base = (bc * H + h) * W;
    const int w0   = w4 * 4;
    const float4 r = *reinterpret_cast<const float4*>(ref + base + w0);
    const float* __restrict__ trow = tgt + base;
    float rv[4] = {r.x, r.y, r.z, r.w};
    float o[4];
#pragma unroll
    for (int j = 0; j < 4; ++j) {
        const int tw = w0 + j - d;
        o[j] = (tw >= 0) ? fabsf(rv[j] - trow[tw]) : 0.0f;
    }
    *reinterpret_cast<float4*>(out + (size_t)i * 4) = make_float4(o[0], o[1], o[2], o[3]);
}

// main path: 4(d) x 4(w) outputs per thread
template <int D, int H, int W>
__device__ __forceinline__ void feat_vol_tile4(const float* __restrict__ ref,
                                               const float* __restrict__ tgt,
                                               float* __restrict__ out, int i) {
    constexpr int W4 = W / 4;
    constexpr int D4 = D / 4;
    constexpr int OSTRIDE = H * W;   // between consecutive d planes

    int w4 = i % W4;
    int t  = i / W4;
    int h  = t % H;  t /= H;
    int d4 = t % D4;
    int bc = t / D4;

    const int w0 = w4 * 4;
    const int d0 = d4 * 4;
    const int e  = w0 - d0;                       // multiple of 4
    const int base = (bc * H + h) * W;
    float* __restrict__ orow = out + ((size_t)(bc * D + d0) * H + h) * W + w0;

    if (e < 0) {                                  // whole 4x4 tile masked
        const float4 z = make_float4(0.f, 0.f, 0.f, 0.f);
#pragma unroll
        for (int k = 0; k < 4; ++k)
            *reinterpret_cast<float4*>(orow + k * OSTRIDE) = z;
        return;
    }

    const float4 r = *reinterpret_cast<const float4*>(ref + base + w0);
    const float rv[4] = {r.x, r.y, r.z, r.w};

    float twin[8];                                // trow[e-4 .. e+3]
    const float4 hi = *reinterpret_cast<const float4*>(tgt + base + e);
    twin[4] = hi.x; twin[5] = hi.y; twin[6] = hi.z; twin[7] = hi.w;
    if (e > 0) {
        const float4 lo = *reinterpret_cast<const float4*>(tgt + base + e - 4);
        twin[0] = lo.x; twin[1] = lo.y; twin[2] = lo.z; twin[3] = lo.w;
    } else {
        twin[0] = twin[1] = twin[2] = twin[3] = 0.f;
    }

#pragma unroll
    for (int k = 0; k < 4; ++k) {                 // d = d0 + k
        float o[4];
#pragma unroll
        for (int j = 0; j < 4; ++j) {             // w = w0 + j
            const float v = fabsf(rv[j] - twin[j - k + 4]);
            o[j] = (e + j - k >= 0) ? v : 0.f;
        }
        *reinterpret_cast<float4*>(orow + k * OSTRIDE) =
            make_float4(o[0], o[1], o[2], o[3]);
    }
}

__global__ void __launch_bounds__(THREADS)
hsmnet_featvol_kernel(const float* __restrict__ c40, const float* __restrict__ c41,
                      const float* __restrict__ c30, const float* __restrict__ c31,
                      const float* __restrict__ c20, const float* __restrict__ c21,
                      const float* __restrict__ c10, const float* __restrict__ c11,
                      float* __restrict__ out) {
    const int gid = blockIdx.x * THREADS + threadIdx.x;

    if (gid < CA) {
        feat_vol_elem<6, 12, 20>(c40, c41, out + O0, gid);
    } else if (gid < CB) {
        feat_vol_tile4<12, 24, 40>(c30, c31, out + O1, gid - CA);
    } else if (gid < CC) {
        feat_vol_tile4<24, 48, 80>(c20, c21, out + O2, gid - CB);
    } else {
        feat_vol_tile4<48, 96, 160>(c10, c11, out + O3, gid - CC);
    }
}

}  // namespace

extern "C" void kernel_launch(void* const* d_in, const int* in_sizes, int n_in,
                              void* d_out, int out_size) {
    const float* c40 = (const float*)d_in[0];
    const float* c41 = (const float*)d_in[1];
    const float* c30 = (const float*)d_in[2];
    const float* c31 = (const float*)d_in[3];
    const float* c20 = (const float*)d_in[4];
    const float* c21 = (const float*)d_in[5];
    const float* c10 = (const float*)d_in[6];
    const float* c11 = (const float*)d_in[7];
    float* out = (float*)d_out;

    hsmnet_featvol_kernel<<<BLOCKS, THREADS>>>(c40, c41, c30, c31,
                                               c20, c21, c10, c11, out);
}